// round 15
// baseline (speedup 1.0000x reference)
#include <cuda_runtime.h>
#include <cstdint>

#define UNUM 100000
#define INUM 200000
#define NTOT 300000
#define NNZE 4000000
#define BSZ  4096
#define DIM  64
#define NLAY 3
#define CDIM2 192             // concat store: layers 1..3 only (layer0 read from inputs)
#define EMAX 96               // padded ELL row capacity (mean deg ~12)
#define RPB  128              // rows per combine block

#define A_STRIDE 132          // words; %32==4 -> conflict-free A frag loads
#define B_STRIDE 72           // words; %32==8 -> conflict-free B frag loads

// keep  <=>  u01(bits) < 0.9f  <=>  bits < 7549747*512 (exact; 0.9f = 7549747/2^23)
#define KEEP_THRESH 0xE6666600u

// ---------------- scratch (static device globals; no allocs allowed) ----------------
__device__ __align__(256) float    g_ego [(size_t)NTOT * DIM];       // 76.8 MB
__device__ __align__(256) float    g_side[(size_t)NTOT * DIM];       // 76.8 MB
__device__ __align__(256) float    g_all [(size_t)NTOT * CDIM2];     // 230 MB
__device__ __align__(256) int2     g_ell [(size_t)NTOT * EMAX];      // 230 MB {col, val bits}
__device__ __align__(256) int      g_cnt [NTOT];
__device__ float g_acc[2];                                           // bpr_sum, reg_sum

// ---------------- threefry2x32 (exact JAX semantics) ----------------
__host__ __device__ __forceinline__ uint32_t rotl32(uint32_t x, int r) {
    return (x << r) | (x >> (32 - r));
}

__host__ __device__ inline void threefry2x32(uint32_t k0, uint32_t k1,
                                             uint32_t x0, uint32_t x1,
                                             uint32_t &o0, uint32_t &o1) {
    uint32_t k2 = k0 ^ k1 ^ 0x1BD11BDAu;
    x0 += k0; x1 += k1;
#define TF_R(r) { x0 += x1; x1 = rotl32(x1, r); x1 ^= x0; }
    TF_R(13) TF_R(15) TF_R(26) TF_R(6)   x0 += k1; x1 += k2 + 1u;
    TF_R(17) TF_R(29) TF_R(16) TF_R(24)  x0 += k2; x1 += k0 + 2u;
    TF_R(13) TF_R(15) TF_R(26) TF_R(6)   x0 += k0; x1 += k1 + 3u;
    TF_R(17) TF_R(29) TF_R(16) TF_R(24)  x0 += k1; x1 += k2 + 4u;
    TF_R(13) TF_R(15) TF_R(26) TF_R(6)   x0 += k2; x1 += k0 + 5u;
#undef TF_R
    o0 = x0; o1 = x1;
}

// Partitionable (counter-mode) bits: threefry(key, (0, i)), 32-bit finisher o0^o1
__device__ __forceinline__ uint32_t rbits_partitionable(uint32_t k0, uint32_t k1, uint32_t i) {
    uint32_t o0, o1;
    threefry2x32(k0, k1, 0u, i, o0, o1);
    return o0 ^ o1;
}

__device__ __forceinline__ uint32_t f2tf32(float x) {
    uint32_t r;
    asm("cvt.rna.tf32.f32 %0, %1;" : "=r"(r) : "f"(x));
    return r;
}

__device__ __forceinline__ void mma_tf32(float c[4], uint32_t a0, uint32_t a1,
                                         uint32_t a2, uint32_t a3,
                                         uint32_t b0, uint32_t b1) {
    asm volatile(
        "mma.sync.aligned.m16n8k8.row.col.f32.tf32.tf32.f32 "
        "{%0,%1,%2,%3}, {%4,%5,%6,%7}, {%8,%9}, {%0,%1,%2,%3};\n"
        : "+f"(c[0]), "+f"(c[1]), "+f"(c[2]), "+f"(c[3])
        : "r"(a0), "r"(a1), "r"(a2), "r"(a3), "r"(b0), "r"(b1));
}

// ---------------- kernels ----------------
// One pass: edge dropout + ELL scatter (dropped edges never stored). Zeroes acc.
__global__ void scatter_kernel(const float* __restrict__ val, const int* __restrict__ row,
                               const int* __restrict__ col, uint32_t k0, uint32_t k1) {
    int e = blockIdx.x * blockDim.x + threadIdx.x;
    if (e == 0) { g_acc[0] = 0.f; g_acc[1] = 0.f; }
    if (e >= NNZE) return;
    if (rbits_partitionable(k0, k1, (uint32_t)e) >= KEEP_THRESH) return;  // dropped
    float v = val[e] * (1.0f / 0.9f);
    int r = row[e];
    int pos = atomicAdd(&g_cnt[r], 1);
    if (pos < EMAX)
        g_ell[(size_t)r * EMAX + pos] = make_int2(col[e], __float_as_int(v));
}

// Atomic-free SpMM: HALF-WARP per row, 16 dim-lanes, 4-way predicated-clamp
// unroll (MLP=4 incl. tail, no cross-lane reduction). Pure gather (no RNG).
__global__ void spmm_kernel(const float* __restrict__ eu, const float* __restrict__ ei) {
    int wp   = (blockIdx.x * blockDim.x + threadIdx.x) >> 5;
    if (wp >= NTOT / 2) return;
    int lane = threadIdx.x & 31;
    int half = lane >> 4;
    int dl   = lane & 15;       // dim quarter (float4)
    int w    = wp * 2 + half;   // this half-warp's row

    int cnt = g_cnt[w];
    if (cnt > EMAX) cnt = EMAX;
    const int2* ep = g_ell + (size_t)w * EMAX;
    float4 acc = make_float4(0.f, 0.f, 0.f, 0.f);
    for (int j = 0; j < cnt; j += 4) {
        int i1 = min(j + 1, cnt - 1);
        int i2 = min(j + 2, cnt - 1);
        int i3 = min(j + 3, cnt - 1);
        int2 c0 = ep[j], c1 = ep[i1], c2 = ep[i2], c3 = ep[i3];
        const float* r0 = (c0.x < UNUM) ? eu + (size_t)c0.x * DIM : ei + (size_t)(c0.x - UNUM) * DIM;
        const float* r1 = (c1.x < UNUM) ? eu + (size_t)c1.x * DIM : ei + (size_t)(c1.x - UNUM) * DIM;
        const float* r2 = (c2.x < UNUM) ? eu + (size_t)c2.x * DIM : ei + (size_t)(c2.x - UNUM) * DIM;
        const float* r3 = (c3.x < UNUM) ? eu + (size_t)c3.x * DIM : ei + (size_t)(c3.x - UNUM) * DIM;
        float4 x0 = ((const float4*)r0)[dl];
        float4 x1 = ((const float4*)r1)[dl];
        float4 x2 = ((const float4*)r2)[dl];
        float4 x3 = ((const float4*)r3)[dl];
        float v0 = __int_as_float(c0.y);
        float v1 = (j + 1 < cnt) ? __int_as_float(c1.y) : 0.f;
        float v2 = (j + 2 < cnt) ? __int_as_float(c2.y) : 0.f;
        float v3 = (j + 3 < cnt) ? __int_as_float(c3.y) : 0.f;
        acc.x += v0 * x0.x + v1 * x1.x + v2 * x2.x + v3 * x3.x;
        acc.y += v0 * x0.y + v1 * x1.y + v2 * x2.y + v3 * x3.y;
        acc.z += v0 * x0.z + v1 * x1.z + v2 * x2.z + v3 * x3.z;
        acc.w += v0 * x0.w + v1 * x1.w + v2 * x2.w + v3 * x3.w;
    }
    ((float4*)(g_side + (size_t)w * DIM))[dl] = acc;
}

// tf32 tensor-core combine + fused dropout/normalize epilogue.
// Mask bits are computed INLINE, interleaved with the mma mainloop (2 threefry
// chains per k16 iteration) to fill the ~70% idle issue slots measured in R10.
__global__ void combine_kernel(const float* __restrict__ Wg, const float* __restrict__ bg,
                               const float* __restrict__ Wb, const float* __restrict__ bb,
                               const float* __restrict__ eu, const float* __restrict__ ei,
                               uint32_t mk0, uint32_t mk1, int layer, int write_ego) {
    extern __shared__ uint32_t smem_u[];
    uint32_t* sA    = smem_u;                              // 128 x A_STRIDE
    uint32_t* sB    = sA + RPB * A_STRIDE;                 // 128 x B_STRIDE
    float*    sbias = (float*)(sB + 128 * B_STRIDE);       // 64

    int tid  = threadIdx.x;
    int row0 = blockIdx.x * RPB;

    // ---- build B (tf32) + bias ----
    for (int i = tid; i < 8192; i += 256) {
        int k = i >> 6, n = i & 63;
        float v = (k < 64) ? Wg[k * 64 + n] : Wb[(k - 64) * 64 + n];
        sB[k * B_STRIDE + n] = f2tf32(v);
    }
    if (tid < 64) sbias[tid] = bg[tid] + bb[tid];

    // ---- build A (tf32): cols 0..63 = side, 64..127 = side*ego ----
    for (int i = tid; i < RPB * 16; i += 256) {
        int r = i >> 4, q = i & 15;
        int gr = row0 + r;
        float4 s = make_float4(0.f, 0.f, 0.f, 0.f), e = s;
        if (gr < NTOT) {
            s = ((const float4*)(g_side + (size_t)gr * DIM))[q];
            const float* erow = (gr < UNUM) ? eu + (size_t)gr * DIM
                                            : ei + (size_t)(gr - UNUM) * DIM;
            e = ((const float4*)erow)[q];
        }
        uint4 us = make_uint4(f2tf32(s.x), f2tf32(s.y), f2tf32(s.z), f2tf32(s.w));
        uint4 ue = make_uint4(f2tf32(s.x * e.x), f2tf32(s.y * e.y),
                              f2tf32(s.z * e.z), f2tf32(s.w * e.w));
        *(uint4*)&sA[r * A_STRIDE + q * 4]      = us;
        *(uint4*)&sA[r * A_STRIDE + 64 + q * 4] = ue;
    }
    __syncthreads();

    int w    = tid >> 5;
    int lane = tid & 31;
    int g    = lane >> 2;       // group id 0..7
    int tg   = lane & 3;        // thread-in-group 0..3
    int r0   = row0 + w * 16 + g;
    int r1   = r0 + 8;

    // accumulators: 8 n-tiles x {c0,c1,c2,c3}
    float c[8][4];
#pragma unroll
    for (int nt = 0; nt < 8; nt++) {
        int col0 = nt * 8 + tg * 2;
        float b0 = sbias[col0], b1 = sbias[col0 + 1];
        c[nt][0] = b0; c[nt][1] = b1;   // row g
        c[nt][2] = b0; c[nt][3] = b1;   // row g+8
    }

    // mainloop with interleaved mask generation:
    // iteration k16 computes keep bit for element (r0, col_m) and (r1, col_m),
    // where col_m = (k16>>1)*8 + tg*2 + (k16&1)  (bit index == nt*2+q).
    uint32_t keep0 = 0, keep1 = 0;
    uint32_t ebase0 = (uint32_t)r0 * 64u + (uint32_t)(tg * 2);
    uint32_t ebase1 = (uint32_t)r1 * 64u + (uint32_t)(tg * 2);
    const uint32_t* Abase = sA + (w * 16 + g) * A_STRIDE + tg;
#pragma unroll 4
    for (int k16 = 0; k16 < 16; k16++) {
        int kb = k16 * 8;
        uint32_t a0 = Abase[kb];
        uint32_t a1 = Abase[8 * A_STRIDE + kb];
        uint32_t a2 = Abase[kb + 4];
        uint32_t a3 = Abase[8 * A_STRIDE + kb + 4];

        uint32_t col_m = (uint32_t)((k16 >> 1) * 8 + (k16 & 1));
        uint32_t kp0 = (rbits_partitionable(mk0, mk1, ebase0 + col_m) < KEEP_THRESH) ? 1u : 0u;
        uint32_t kp1 = (rbits_partitionable(mk0, mk1, ebase1 + col_m) < KEEP_THRESH) ? 1u : 0u;
        keep0 |= kp0 << k16;
        keep1 |= kp1 << k16;

        const uint32_t* Bb = sB + (kb + tg) * B_STRIDE + g;
#pragma unroll
        for (int nt = 0; nt < 8; nt++) {
            uint32_t b0 = Bb[nt * 8];
            uint32_t b1 = Bb[4 * B_STRIDE + nt * 8];
            mma_tf32(c[nt], a0, a1, a2, a3, b0, b1);
        }
    }

    // ---- fused epilogue: leaky_relu -> dropout (inline bits) -> L2 norm ----
    float ss0 = 0.f, ss1 = 0.f;
#pragma unroll
    for (int nt = 0; nt < 8; nt++) {
#pragma unroll
        for (int q = 0; q < 2; q++) {
            int bit = nt * 2 + q;
            float a = c[nt][q];
            a = (a >= 0.f) ? a : 0.2f * a;
            a = ((keep0 >> bit) & 1u) ? a * (1.0f / 0.9f) : 0.f;
            c[nt][q] = a;
            ss0 += a * a;
            float b = c[nt][2 + q];
            b = (b >= 0.f) ? b : 0.2f * b;
            b = ((keep1 >> bit) & 1u) ? b * (1.0f / 0.9f) : 0.f;
            c[nt][2 + q] = b;
            ss1 += b * b;
        }
    }
    // reduce over the 4 threads (tg) holding this row's 64 cols
    ss0 += __shfl_xor_sync(0xFFFFFFFFu, ss0, 1);
    ss0 += __shfl_xor_sync(0xFFFFFFFFu, ss0, 2);
    ss1 += __shfl_xor_sync(0xFFFFFFFFu, ss1, 1);
    ss1 += __shfl_xor_sync(0xFFFFFFFFu, ss1, 2);
    float inv0 = 1.0f / fmaxf(sqrtf(ss0), 1e-12f);
    float inv1 = 1.0f / fmaxf(sqrtf(ss1), 1e-12f);

    float* all0 = g_all + (size_t)r0 * CDIM2 + (size_t)layer * DIM;
    float* all1 = g_all + (size_t)r1 * CDIM2 + (size_t)layer * DIM;
#pragma unroll
    for (int nt = 0; nt < 8; nt++) {
        int col0 = nt * 8 + tg * 2;
        if (r0 < NTOT) {
            *(float2*)(all0 + col0) = make_float2(c[nt][0] * inv0, c[nt][1] * inv0);
            if (write_ego)
                *(float2*)(g_ego + (size_t)r0 * DIM + col0) = make_float2(c[nt][0], c[nt][1]);
        }
        if (r1 < NTOT) {
            *(float2*)(all1 + col0) = make_float2(c[nt][2] * inv1, c[nt][3] * inv1);
            if (write_ego)
                *(float2*)(g_ego + (size_t)r1 * DIM + col0) = make_float2(c[nt][2], c[nt][3]);
        }
    }
}

// warp per sample: BPR + reg partial sums. Concat = [raw emb | g_all(192)].
__global__ void loss_kernel(const float* __restrict__ ue0, const float* __restrict__ ie0,
                            const int* __restrict__ uid, const int* __restrict__ pid,
                            const int* __restrict__ nid) {
    int w    = (blockIdx.x * blockDim.x + threadIdx.x) >> 5;
    int lane = threadIdx.x & 31;
    if (w >= BSZ) return;
    int u = uid[w], p = pid[w], n = nid[w];
    const float* au = (lane < 8) ? ue0 + (size_t)u * DIM + lane * 8
                                 : g_all + (size_t)u * CDIM2 + lane * 8 - 64;
    const float* bp = (lane < 8) ? ie0 + (size_t)p * DIM + lane * 8
                                 : g_all + (size_t)(UNUM + p) * CDIM2 + lane * 8 - 64;
    const float* bn = (lane < 8) ? ie0 + (size_t)n * DIM + lane * 8
                                 : g_all + (size_t)(UNUM + n) * CDIM2 + lane * 8 - 64;
    float pos = 0.f, neg = 0.f;
#pragma unroll
    for (int t = 0; t < 2; t++) {
        float4 a = ((const float4*)au)[t];
        float4 b = ((const float4*)bp)[t];
        float4 c = ((const float4*)bn)[t];
        pos += a.x * b.x + a.y * b.y + a.z * b.z + a.w * b.w;
        neg += a.x * c.x + a.y * c.y + a.z * c.z + a.w * c.w;
    }
    float2 a0 = ((const float2*)(ue0 + (size_t)u * DIM))[lane];
    float2 b0 = ((const float2*)(ie0 + (size_t)p * DIM))[lane];
    float2 c0 = ((const float2*)(ie0 + (size_t)n * DIM))[lane];
    float rg = a0.x * a0.x + a0.y * a0.y + b0.x * b0.x + b0.y * b0.y + c0.x * c0.x + c0.y * c0.y;
#pragma unroll
    for (int o = 16; o; o >>= 1) {
        pos += __shfl_xor_sync(0xFFFFFFFFu, pos, o);
        neg += __shfl_xor_sync(0xFFFFFFFFu, neg, o);
        rg  += __shfl_xor_sync(0xFFFFFFFFu, rg,  o);
    }
    if (lane == 0) {
        float x = pos - neg;
        float ls = fminf(x, 0.f) - log1pf(expf(-fabsf(x)));  // stable log_sigmoid
        atomicAdd(&g_acc[0], ls);
        atomicAdd(&g_acc[1], rg);
    }
}

__global__ void fin_kernel(float* out, int osz) {
    float bpr = -g_acc[0] / (float)BSZ;
    float reg = 1e-4f * 0.5f * g_acc[1] / (float)BSZ;
    if (osz >= 3) { out[0] = bpr + reg; out[1] = bpr; out[2] = reg; }
    else          { out[0] = bpr + reg; }
}

// ---------------- launch ----------------
extern "C" void kernel_launch(void* const* d_in, const int* in_sizes, int n_in,
                              void* d_out, int out_size) {
    const float* user_emb = (const float*)d_in[0];
    const float* item_emb = (const float*)d_in[1];
    const float* W_gc     = (const float*)d_in[2];
    const float* b_gc     = (const float*)d_in[3];
    const float* W_bi     = (const float*)d_in[4];
    const float* b_bi     = (const float*)d_in[5];
    const float* val      = (const float*)d_in[6];
    const int*   row      = (const int*)d_in[7];
    const int*   col      = (const int*)d_in[8];
    const int*   uid      = (const int*)d_in[9];
    const int*   pid      = (const int*)d_in[10];
    const int*   nid      = (const int*)d_in[11];

    // derived threefry keys: base key = (0, 42); fold_in(d) = threefry(key, (0, d))
    uint32_t ke0, ke1;
    threefry2x32(0u, 42u, 0u, 0u, ke0, ke1);
    uint32_t mk0[NLAY], mk1[NLAY];
    for (int k = 0; k < NLAY; k++)
        threefry2x32(0u, 42u, 0u, (uint32_t)(k + 1), mk0[k], mk1[k]);

    const size_t SMEM = (RPB * A_STRIDE + 128 * B_STRIDE) * 4 + 64 * 4;  // ~104.7 KB
    static bool attr_set = false;
    if (!attr_set) {
        cudaFuncSetAttribute(combine_kernel, cudaFuncAttributeMaxDynamicSharedMemorySize, (int)SMEM);
        attr_set = true;
    }

    void* cnt_ptr = nullptr;
    cudaGetSymbolAddress(&cnt_ptr, g_cnt);
    float* g_ego_ptr = nullptr;
    { void* tmp = nullptr; cudaGetSymbolAddress(&tmp, g_ego); g_ego_ptr = (float*)tmp; }

    cudaMemsetAsync(cnt_ptr, 0, NTOT * sizeof(int));
    scatter_kernel<<<(NNZE + 255) / 256, 256>>>(val, row, col, ke0, ke1);

    for (int k = 0; k < NLAY; k++) {
        const float* eu = (k == 0) ? user_emb : g_ego_ptr;
        const float* ei = (k == 0) ? item_emb : g_ego_ptr + (size_t)UNUM * DIM;
        spmm_kernel<<<((NTOT / 2) * 32 + 255) / 256, 256>>>(eu, ei);
        combine_kernel<<<(NTOT + RPB - 1) / RPB, 256, SMEM>>>(
            W_gc + k * 4096, b_gc + k * 64, W_bi + k * 4096, b_bi + k * 64,
            eu, ei, mk0[k], mk1[k], k, (k != NLAY - 1) ? 1 : 0);
    }

    loss_kernel<<<(BSZ * 32 + 255) / 256, 256>>>(user_emb, item_emb, uid, pid, nid);
    fin_kernel<<<1, 1>>>((float*)d_out, out_size);
}

// round 16
// speedup vs baseline: 1.1734x; 1.1734x over previous
#include <cuda_runtime.h>
#include <cuda_fp16.h>
#include <cstdint>

#define UNUM 100000
#define INUM 200000
#define NTOT 300000
#define NNZE 4000000
#define BSZ  4096
#define DIM  64
#define NLAY 3
#define CDIM2 192             // concat store: layers 1..3 only (layer0 read from inputs)
#define EMAX 96               // padded ELL row capacity (mean deg ~12)
#define RPB  128              // rows per combine block
#define NELEM (NTOT * DIM)    // 19,200,000 elems per layer
#define NWORD (NELEM / 32)    // 600,000 mask words per layer

#define A_STRIDE 132          // words; %32==4 -> conflict-free A frag loads
#define B_STRIDE 72           // words; %32==8 -> conflict-free B frag loads

// keep  <=>  u01(bits) < 0.9f  <=>  bits < 7549747*512 (exact; 0.9f = 7549747/2^23)
#define KEEP_THRESH 0xE6666600u

// ---------------- scratch (static device globals; no allocs allowed) ----------------
__device__ __align__(256) __half    g_ego_h[(size_t)NTOT * DIM];     // 38.4 MB (L2-resident)
__device__ __align__(256) float     g_side [(size_t)NTOT * DIM];     // 76.8 MB
__device__ __align__(256) float     g_all  [(size_t)NTOT * CDIM2];   // 230 MB
__device__ __align__(256) int2      g_ell  [(size_t)NTOT * EMAX];    // 230 MB {col, val bits}
__device__ __align__(256) int       g_cnt  [NTOT];
__device__ __align__(256) uint32_t  g_mask [(size_t)NLAY * NWORD];   // 7.2 MB bit-packed
__device__ float g_acc[2];                                           // bpr_sum, reg_sum

// ---------------- threefry2x32 (exact JAX semantics) ----------------
__host__ __device__ __forceinline__ uint32_t rotl32(uint32_t x, int r) {
    return (x << r) | (x >> (32 - r));
}

__host__ __device__ inline void threefry2x32(uint32_t k0, uint32_t k1,
                                             uint32_t x0, uint32_t x1,
                                             uint32_t &o0, uint32_t &o1) {
    uint32_t k2 = k0 ^ k1 ^ 0x1BD11BDAu;
    x0 += k0; x1 += k1;
#define TF_R(r) { x0 += x1; x1 = rotl32(x1, r); x1 ^= x0; }
    TF_R(13) TF_R(15) TF_R(26) TF_R(6)   x0 += k1; x1 += k2 + 1u;
    TF_R(17) TF_R(29) TF_R(16) TF_R(24)  x0 += k2; x1 += k0 + 2u;
    TF_R(13) TF_R(15) TF_R(26) TF_R(6)   x0 += k0; x1 += k1 + 3u;
    TF_R(17) TF_R(29) TF_R(16) TF_R(24)  x0 += k1; x1 += k2 + 4u;
    TF_R(13) TF_R(15) TF_R(26) TF_R(6)   x0 += k2; x1 += k0 + 5u;
#undef TF_R
    o0 = x0; o1 = x1;
}

// Partitionable (counter-mode) bits: threefry(key, (0, i)), 32-bit finisher o0^o1
__device__ __forceinline__ uint32_t rbits_partitionable(uint32_t k0, uint32_t k1, uint32_t i) {
    uint32_t o0, o1;
    threefry2x32(k0, k1, 0u, i, o0, o1);
    return o0 ^ o1;
}

__device__ __forceinline__ uint32_t f2tf32(float x) {
    uint32_t r;
    asm("cvt.rna.tf32.f32 %0, %1;" : "=r"(r) : "f"(x));
    return r;
}

__device__ __forceinline__ void mma_tf32(float c[4], uint32_t a0, uint32_t a1,
                                         uint32_t a2, uint32_t a3,
                                         uint32_t b0, uint32_t b1) {
    asm volatile(
        "mma.sync.aligned.m16n8k8.row.col.f32.tf32.tf32.f32 "
        "{%0,%1,%2,%3}, {%4,%5,%6,%7}, {%8,%9}, {%0,%1,%2,%3};\n"
        : "+f"(c[0]), "+f"(c[1]), "+f"(c[2]), "+f"(c[3])
        : "r"(a0), "r"(a1), "r"(a2), "r"(a3), "r"(b0), "r"(b1));
}

// unpack uint2 (4 halves) -> 4 floats
__device__ __forceinline__ float4 h4_to_f4(uint2 u) {
    __half2 h0 = *(__half2*)&u.x;
    __half2 h1 = *(__half2*)&u.y;
    float2 a = __half22float2(h0);
    float2 b = __half22float2(h1);
    return make_float4(a.x, a.y, b.x, b.y);
}

// ---------------- kernels ----------------
// Convert raw embeddings to the fp16 ego mirror + zero acc.
__global__ void init_kernel(const float* __restrict__ ue, const float* __restrict__ ie) {
    int i = blockIdx.x * blockDim.x + threadIdx.x;
    if (i == 0) { g_acc[0] = 0.f; g_acc[1] = 0.f; }
    if (i >= NELEM) return;
    float v = (i < UNUM * DIM) ? ue[i] : ie[i - UNUM * DIM];
    g_ego_h[i] = __float2half(v);
}

// One pass: edge dropout + ELL scatter (dropped edges never stored).
__global__ void scatter_kernel(const float* __restrict__ val, const int* __restrict__ row,
                               const int* __restrict__ col, uint32_t k0, uint32_t k1) {
    int e = blockIdx.x * blockDim.x + threadIdx.x;
    if (e >= NNZE) return;
    if (rbits_partitionable(k0, k1, (uint32_t)e) >= KEEP_THRESH) return;  // dropped
    float v = val[e] * (1.0f / 0.9f);
    int r = row[e];
    int pos = atomicAdd(&g_cnt[r], 1);
    if (pos < EMAX)
        g_ell[(size_t)r * EMAX + pos] = make_int2(col[e], __float_as_int(v));
}

// Atomic-free SpMM: HALF-WARP per row, 16 dim-lanes, 4-way predicated-clamp
// unroll (MLP=4 incl. tail). fp16 gather (8 B/lane/edge, L2-resident table).
// ALSO generates this layer's dropout mask (hidden in gather stalls — measured
// ~4 us in R14/R15 A/B).
__global__ void spmm_kernel(uint32_t mk0, uint32_t mk1, int layer) {
    int wp   = (blockIdx.x * blockDim.x + threadIdx.x) >> 5;
    if (wp >= NTOT / 2) return;
    int lane = threadIdx.x & 31;
    int half = lane >> 4;
    int dl   = lane & 15;       // dim quarter (4 halves each)
    int w    = wp * 2 + half;   // this half-warp's row

    // ---- mask generation: 128 elems [128wp, 128wp+128) -> words 4wp..4wp+3 ----
    uint32_t eb = (uint32_t)wp * 128u + (uint32_t)lane;
#pragma unroll
    for (int q = 0; q < 4; q++) {
        bool keep = rbits_partitionable(mk0, mk1, eb + (uint32_t)(q * 32)) < KEEP_THRESH;
        uint32_t mwd = __ballot_sync(0xFFFFFFFFu, keep);
        if (lane == 0) g_mask[(size_t)layer * NWORD + wp * 4 + q] = mwd;
    }

    // ---- gather (4 edges in flight; tail clamps index, zeroes value) ----
    int cnt = g_cnt[w];
    if (cnt > EMAX) cnt = EMAX;
    const int2* ep = g_ell + (size_t)w * EMAX;
    float4 acc = make_float4(0.f, 0.f, 0.f, 0.f);
    for (int j = 0; j < cnt; j += 4) {
        int i1 = min(j + 1, cnt - 1);
        int i2 = min(j + 2, cnt - 1);
        int i3 = min(j + 3, cnt - 1);
        int2 c0 = ep[j], c1 = ep[i1], c2 = ep[i2], c3 = ep[i3];
        uint2 u0 = ((const uint2*)(g_ego_h + (size_t)c0.x * DIM))[dl];
        uint2 u1 = ((const uint2*)(g_ego_h + (size_t)c1.x * DIM))[dl];
        uint2 u2 = ((const uint2*)(g_ego_h + (size_t)c2.x * DIM))[dl];
        uint2 u3 = ((const uint2*)(g_ego_h + (size_t)c3.x * DIM))[dl];
        float4 x0 = h4_to_f4(u0);
        float4 x1 = h4_to_f4(u1);
        float4 x2 = h4_to_f4(u2);
        float4 x3 = h4_to_f4(u3);
        float v0 = __int_as_float(c0.y);
        float v1 = (j + 1 < cnt) ? __int_as_float(c1.y) : 0.f;
        float v2 = (j + 2 < cnt) ? __int_as_float(c2.y) : 0.f;
        float v3 = (j + 3 < cnt) ? __int_as_float(c3.y) : 0.f;
        acc.x += v0 * x0.x + v1 * x1.x + v2 * x2.x + v3 * x3.x;
        acc.y += v0 * x0.y + v1 * x1.y + v2 * x2.y + v3 * x3.y;
        acc.z += v0 * x0.z + v1 * x1.z + v2 * x2.z + v3 * x3.z;
        acc.w += v0 * x0.w + v1 * x1.w + v2 * x2.w + v3 * x3.w;
    }
    ((float4*)(g_side + (size_t)w * DIM))[dl] = acc;
}

// tf32 tensor-core combine + fused dropout/normalize epilogue (mask from g_mask).
// C[128x64] = A[128x128] @ B[128x64] + bias -> leaky_relu -> mask dropout
//  -> dropped ego (fp16 mirror, unless last layer) + L2-normalized concat (g_all).
__global__ void combine_kernel(const float* __restrict__ Wg, const float* __restrict__ bg,
                               const float* __restrict__ Wb, const float* __restrict__ bb,
                               int layer, int write_ego) {
    extern __shared__ uint32_t smem_u[];
    uint32_t* sA    = smem_u;                              // 128 x A_STRIDE
    uint32_t* sB    = sA + RPB * A_STRIDE;                 // 128 x B_STRIDE
    float*    sbias = (float*)(sB + 128 * B_STRIDE);       // 64

    int tid  = threadIdx.x;
    int row0 = blockIdx.x * RPB;

    // ---- build B (tf32) + bias ----
    for (int i = tid; i < 8192; i += 256) {
        int k = i >> 6, n = i & 63;
        float v = (k < 64) ? Wg[k * 64 + n] : Wb[(k - 64) * 64 + n];
        sB[k * B_STRIDE + n] = f2tf32(v);
    }
    if (tid < 64) sbias[tid] = bg[tid] + bb[tid];

    // ---- build A (tf32): cols 0..63 = side, 64..127 = side*ego (ego from fp16) ----
    for (int i = tid; i < RPB * 16; i += 256) {
        int r = i >> 4, q = i & 15;
        int gr = row0 + r;
        float4 s = make_float4(0.f, 0.f, 0.f, 0.f);
        float4 e = s;
        if (gr < NTOT) {
            s = ((const float4*)(g_side + (size_t)gr * DIM))[q];
            e = h4_to_f4(((const uint2*)(g_ego_h + (size_t)gr * DIM))[q]);
        }
        uint4 us = make_uint4(f2tf32(s.x), f2tf32(s.y), f2tf32(s.z), f2tf32(s.w));
        uint4 ue = make_uint4(f2tf32(s.x * e.x), f2tf32(s.y * e.y),
                              f2tf32(s.z * e.z), f2tf32(s.w * e.w));
        *(uint4*)&sA[r * A_STRIDE + q * 4]      = us;
        *(uint4*)&sA[r * A_STRIDE + 64 + q * 4] = ue;
    }
    __syncthreads();

    int w    = tid >> 5;
    int lane = tid & 31;
    int g    = lane >> 2;       // group id 0..7
    int tg   = lane & 3;        // thread-in-group 0..3

    // accumulators: 8 n-tiles x {c0,c1,c2,c3}
    float c[8][4];
#pragma unroll
    for (int nt = 0; nt < 8; nt++) {
        int col0 = nt * 8 + tg * 2;
        float b0 = sbias[col0], b1 = sbias[col0 + 1];
        c[nt][0] = b0; c[nt][1] = b1;   // row g
        c[nt][2] = b0; c[nt][3] = b1;   // row g+8
    }

    const uint32_t* Abase = sA + (w * 16 + g) * A_STRIDE + tg;
#pragma unroll
    for (int k16 = 0; k16 < 16; k16++) {
        int kb = k16 * 8;
        uint32_t a0 = Abase[kb];
        uint32_t a1 = Abase[8 * A_STRIDE + kb];
        uint32_t a2 = Abase[kb + 4];
        uint32_t a3 = Abase[8 * A_STRIDE + kb + 4];
        const uint32_t* Bb = sB + (kb + tg) * B_STRIDE + g;
#pragma unroll
        for (int nt = 0; nt < 8; nt++) {
            uint32_t b0 = Bb[nt * 8];
            uint32_t b1 = Bb[4 * B_STRIDE + nt * 8];
            mma_tf32(c[nt], a0, a1, a2, a3, b0, b1);
        }
    }

    // ---- fused epilogue: leaky_relu -> dropout (bitmask) -> L2 norm ----
    int r0 = row0 + w * 16 + g;
    int r1 = r0 + 8;
    const uint32_t* mb = g_mask + (size_t)layer * NWORD;
    uint2 m0 = (r0 < NTOT) ? *(const uint2*)&mb[2 * r0] : make_uint2(0u, 0u);
    uint2 m1 = (r1 < NTOT) ? *(const uint2*)&mb[2 * r1] : make_uint2(0u, 0u);

    float ss0 = 0.f, ss1 = 0.f;
#pragma unroll
    for (int nt = 0; nt < 8; nt++) {
        int col0 = nt * 8 + tg * 2;
#pragma unroll
        for (int q = 0; q < 2; q++) {
            int col = col0 + q;
            uint32_t bit0 = ((col < 32 ? m0.x : m0.y) >> (col & 31)) & 1u;
            uint32_t bit1 = ((col < 32 ? m1.x : m1.y) >> (col & 31)) & 1u;
            float a = c[nt][q];
            a = (a >= 0.f) ? a : 0.2f * a;
            a = bit0 ? a * (1.0f / 0.9f) : 0.f;
            c[nt][q] = a;
            ss0 += a * a;
            float b = c[nt][2 + q];
            b = (b >= 0.f) ? b : 0.2f * b;
            b = bit1 ? b * (1.0f / 0.9f) : 0.f;
            c[nt][2 + q] = b;
            ss1 += b * b;
        }
    }
    // reduce over the 4 threads (tg) holding this row's 64 cols
    ss0 += __shfl_xor_sync(0xFFFFFFFFu, ss0, 1);
    ss0 += __shfl_xor_sync(0xFFFFFFFFu, ss0, 2);
    ss1 += __shfl_xor_sync(0xFFFFFFFFu, ss1, 1);
    ss1 += __shfl_xor_sync(0xFFFFFFFFu, ss1, 2);
    float inv0 = 1.0f / fmaxf(sqrtf(ss0), 1e-12f);
    float inv1 = 1.0f / fmaxf(sqrtf(ss1), 1e-12f);

    float* all0 = g_all + (size_t)r0 * CDIM2 + (size_t)layer * DIM;
    float* all1 = g_all + (size_t)r1 * CDIM2 + (size_t)layer * DIM;
#pragma unroll
    for (int nt = 0; nt < 8; nt++) {
        int col0 = nt * 8 + tg * 2;
        if (r0 < NTOT) {
            *(float2*)(all0 + col0) = make_float2(c[nt][0] * inv0, c[nt][1] * inv0);
            if (write_ego)
                *(__half2*)(g_ego_h + (size_t)r0 * DIM + col0) =
                    __floats2half2_rn(c[nt][0], c[nt][1]);
        }
        if (r1 < NTOT) {
            *(float2*)(all1 + col0) = make_float2(c[nt][2] * inv1, c[nt][3] * inv1);
            if (write_ego)
                *(__half2*)(g_ego_h + (size_t)r1 * DIM + col0) =
                    __floats2half2_rn(c[nt][2], c[nt][3]);
        }
    }
}

// warp per sample: BPR + reg partial sums. Concat = [raw emb | g_all(192)].
__global__ void loss_kernel(const float* __restrict__ ue0, const float* __restrict__ ie0,
                            const int* __restrict__ uid, const int* __restrict__ pid,
                            const int* __restrict__ nid) {
    int w    = (blockIdx.x * blockDim.x + threadIdx.x) >> 5;
    int lane = threadIdx.x & 31;
    if (w >= BSZ) return;
    int u = uid[w], p = pid[w], n = nid[w];
    const float* au = (lane < 8) ? ue0 + (size_t)u * DIM + lane * 8
                                 : g_all + (size_t)u * CDIM2 + lane * 8 - 64;
    const float* bp = (lane < 8) ? ie0 + (size_t)p * DIM + lane * 8
                                 : g_all + (size_t)(UNUM + p) * CDIM2 + lane * 8 - 64;
    const float* bn = (lane < 8) ? ie0 + (size_t)n * DIM + lane * 8
                                 : g_all + (size_t)(UNUM + n) * CDIM2 + lane * 8 - 64;
    float pos = 0.f, neg = 0.f;
#pragma unroll
    for (int t = 0; t < 2; t++) {
        float4 a = ((const float4*)au)[t];
        float4 b = ((const float4*)bp)[t];
        float4 c = ((const float4*)bn)[t];
        pos += a.x * b.x + a.y * b.y + a.z * b.z + a.w * b.w;
        neg += a.x * c.x + a.y * c.y + a.z * c.z + a.w * c.w;
    }
    float2 a0 = ((const float2*)(ue0 + (size_t)u * DIM))[lane];
    float2 b0 = ((const float2*)(ie0 + (size_t)p * DIM))[lane];
    float2 c0 = ((const float2*)(ie0 + (size_t)n * DIM))[lane];
    float rg = a0.x * a0.x + a0.y * a0.y + b0.x * b0.x + b0.y * b0.y + c0.x * c0.x + c0.y * c0.y;
#pragma unroll
    for (int o = 16; o; o >>= 1) {
        pos += __shfl_xor_sync(0xFFFFFFFFu, pos, o);
        neg += __shfl_xor_sync(0xFFFFFFFFu, neg, o);
        rg  += __shfl_xor_sync(0xFFFFFFFFu, rg,  o);
    }
    if (lane == 0) {
        float x = pos - neg;
        float ls = fminf(x, 0.f) - log1pf(expf(-fabsf(x)));  // stable log_sigmoid
        atomicAdd(&g_acc[0], ls);
        atomicAdd(&g_acc[1], rg);
    }
}

__global__ void fin_kernel(float* out, int osz) {
    float bpr = -g_acc[0] / (float)BSZ;
    float reg = 1e-4f * 0.5f * g_acc[1] / (float)BSZ;
    if (osz >= 3) { out[0] = bpr + reg; out[1] = bpr; out[2] = reg; }
    else          { out[0] = bpr + reg; }
}

// ---------------- launch ----------------
extern "C" void kernel_launch(void* const* d_in, const int* in_sizes, int n_in,
                              void* d_out, int out_size) {
    const float* user_emb = (const float*)d_in[0];
    const float* item_emb = (const float*)d_in[1];
    const float* W_gc     = (const float*)d_in[2];
    const float* b_gc     = (const float*)d_in[3];
    const float* W_bi     = (const float*)d_in[4];
    const float* b_bi     = (const float*)d_in[5];
    const float* val      = (const float*)d_in[6];
    const int*   row      = (const int*)d_in[7];
    const int*   col      = (const int*)d_in[8];
    const int*   uid      = (const int*)d_in[9];
    const int*   pid      = (const int*)d_in[10];
    const int*   nid      = (const int*)d_in[11];

    // derived threefry keys: base key = (0, 42); fold_in(d) = threefry(key, (0, d))
    uint32_t ke0, ke1;
    threefry2x32(0u, 42u, 0u, 0u, ke0, ke1);
    uint32_t mk0[NLAY], mk1[NLAY];
    for (int k = 0; k < NLAY; k++)
        threefry2x32(0u, 42u, 0u, (uint32_t)(k + 1), mk0[k], mk1[k]);

    const size_t SMEM = (RPB * A_STRIDE + 128 * B_STRIDE) * 4 + 64 * 4;  // ~104.7 KB
    static bool attr_set = false;
    if (!attr_set) {
        cudaFuncSetAttribute(combine_kernel, cudaFuncAttributeMaxDynamicSharedMemorySize, (int)SMEM);
        attr_set = true;
    }

    void* cnt_ptr = nullptr;
    cudaGetSymbolAddress(&cnt_ptr, g_cnt);

    cudaMemsetAsync(cnt_ptr, 0, NTOT * sizeof(int));
    init_kernel<<<(NELEM + 255) / 256, 256>>>(user_emb, item_emb);
    scatter_kernel<<<(NNZE + 255) / 256, 256>>>(val, row, col, ke0, ke1);

    for (int k = 0; k < NLAY; k++) {
        spmm_kernel<<<((NTOT / 2) * 32 + 255) / 256, 256>>>(mk0[k], mk1[k], k);
        combine_kernel<<<(NTOT + RPB - 1) / RPB, 256, SMEM>>>(
            W_gc + k * 4096, b_gc + k * 64, W_bi + k * 4096, b_bi + k * 64,
            k, (k != NLAY - 1) ? 1 : 0);
    }

    loss_kernel<<<(BSZ * 32 + 255) / 256, 256>>>(user_emb, item_emb, uid, pid, nid);
    fin_kernel<<<1, 1>>>((float*)d_out, out_size);
}

// round 17
// speedup vs baseline: 1.4122x; 1.2035x over previous
#include <cuda_runtime.h>
#include <cuda_fp16.h>
#include <cstdint>

#define UNUM 100000
#define INUM 200000
#define NTOT 300000
#define NNZE 4000000
#define BSZ  4096
#define DIM  64
#define NLAY 3
#define CDIM2 192             // concat store: layers 1..3 only (layer0 read from inputs)
#define EMAX 96               // padded ELL row capacity (mean deg ~12)
#define RPB  128              // rows per combine block
#define NELEM (NTOT * DIM)    // 19,200,000 elems per layer
#define NWORD (NELEM / 32)    // 600,000 mask words per layer

#define AH 136                // A row stride in halves (68 words; 68%32==4 -> conflict-free)
#define BH 136                // Bt row stride in halves

// keep  <=>  u01(bits) < 0.9f  <=>  bits < 7549747*512 (exact; 0.9f = 7549747/2^23)
#define KEEP_THRESH 0xE6666600u

// ---------------- scratch (static device globals; no allocs allowed) ----------------
__device__ __align__(256) __half    g_ego_h [(size_t)NTOT * DIM];    // 38.4 MB
__device__ __align__(256) __half    g_side_h[(size_t)NTOT * DIM];    // 38.4 MB
__device__ __align__(256) float     g_all   [(size_t)NTOT * CDIM2];  // 230 MB
__device__ __align__(256) int2      g_ell   [(size_t)NTOT * EMAX];   // 230 MB {col, val bits}
__device__ __align__(256) int       g_cnt   [NTOT];
__device__ __align__(256) uint32_t  g_mask  [(size_t)NLAY * NWORD];  // 7.2 MB bit-packed
__device__ float g_acc[2];                                           // bpr_sum, reg_sum

// ---------------- threefry2x32 (exact JAX semantics) ----------------
__host__ __device__ __forceinline__ uint32_t rotl32(uint32_t x, int r) {
    return (x << r) | (x >> (32 - r));
}

__host__ __device__ inline void threefry2x32(uint32_t k0, uint32_t k1,
                                             uint32_t x0, uint32_t x1,
                                             uint32_t &o0, uint32_t &o1) {
    uint32_t k2 = k0 ^ k1 ^ 0x1BD11BDAu;
    x0 += k0; x1 += k1;
#define TF_R(r) { x0 += x1; x1 = rotl32(x1, r); x1 ^= x0; }
    TF_R(13) TF_R(15) TF_R(26) TF_R(6)   x0 += k1; x1 += k2 + 1u;
    TF_R(17) TF_R(29) TF_R(16) TF_R(24)  x0 += k2; x1 += k0 + 2u;
    TF_R(13) TF_R(15) TF_R(26) TF_R(6)   x0 += k0; x1 += k1 + 3u;
    TF_R(17) TF_R(29) TF_R(16) TF_R(24)  x0 += k1; x1 += k2 + 4u;
    TF_R(13) TF_R(15) TF_R(26) TF_R(6)   x0 += k2; x1 += k0 + 5u;
#undef TF_R
    o0 = x0; o1 = x1;
}

// Partitionable (counter-mode) bits: threefry(key, (0, i)), 32-bit finisher o0^o1
__device__ __forceinline__ uint32_t rbits_partitionable(uint32_t k0, uint32_t k1, uint32_t i) {
    uint32_t o0, o1;
    threefry2x32(k0, k1, 0u, i, o0, o1);
    return o0 ^ o1;
}

// fp16 mma m16n8k16 (fp32 accumulate)
__device__ __forceinline__ void mma_f16(float c[4], uint32_t a0, uint32_t a1,
                                        uint32_t a2, uint32_t a3,
                                        uint32_t b0, uint32_t b1) {
    asm volatile(
        "mma.sync.aligned.m16n8k16.row.col.f32.f16.f16.f32 "
        "{%0,%1,%2,%3}, {%4,%5,%6,%7}, {%8,%9}, {%0,%1,%2,%3};\n"
        : "+f"(c[0]), "+f"(c[1]), "+f"(c[2]), "+f"(c[3])
        : "r"(a0), "r"(a1), "r"(a2), "r"(a3), "r"(b0), "r"(b1));
}

// unpack uint2 (4 halves) -> 4 floats
__device__ __forceinline__ float4 h4_to_f4(uint2 u) {
    __half2 h0 = *(__half2*)&u.x;
    __half2 h1 = *(__half2*)&u.y;
    float2 a = __half22float2(h0);
    float2 b = __half22float2(h1);
    return make_float4(a.x, a.y, b.x, b.y);
}

// ---------------- kernels ----------------
// Convert raw embeddings to the fp16 ego mirror + zero acc.
__global__ void init_kernel(const float* __restrict__ ue, const float* __restrict__ ie) {
    int i = blockIdx.x * blockDim.x + threadIdx.x;
    if (i == 0) { g_acc[0] = 0.f; g_acc[1] = 0.f; }
    if (i >= NELEM) return;
    float v = (i < UNUM * DIM) ? ue[i] : ie[i - UNUM * DIM];
    g_ego_h[i] = __float2half(v);
}

// One pass: edge dropout + ELL scatter (dropped edges never stored).
__global__ void scatter_kernel(const float* __restrict__ val, const int* __restrict__ row,
                               const int* __restrict__ col, uint32_t k0, uint32_t k1) {
    int e = blockIdx.x * blockDim.x + threadIdx.x;
    if (e >= NNZE) return;
    if (rbits_partitionable(k0, k1, (uint32_t)e) >= KEEP_THRESH) return;  // dropped
    float v = val[e] * (1.0f / 0.9f);
    int r = row[e];
    int pos = atomicAdd(&g_cnt[r], 1);
    if (pos < EMAX)
        g_ell[(size_t)r * EMAX + pos] = make_int2(col[e], __float_as_int(v));
}

// Atomic-free SpMM: HALF-WARP per row, 16 dim-lanes, 4-way predicated-clamp
// unroll. fp16 gather + fp16 side store. Inline maskgen (hidden in stalls).
__global__ void spmm_kernel(uint32_t mk0, uint32_t mk1, int layer) {
    int wp   = (blockIdx.x * blockDim.x + threadIdx.x) >> 5;
    if (wp >= NTOT / 2) return;
    int lane = threadIdx.x & 31;
    int half = lane >> 4;
    int dl   = lane & 15;       // dim quarter (4 halves each)
    int w    = wp * 2 + half;   // this half-warp's row

    // ---- mask generation: 128 elems [128wp, 128wp+128) -> words 4wp..4wp+3 ----
    uint32_t eb = (uint32_t)wp * 128u + (uint32_t)lane;
#pragma unroll
    for (int q = 0; q < 4; q++) {
        bool keep = rbits_partitionable(mk0, mk1, eb + (uint32_t)(q * 32)) < KEEP_THRESH;
        uint32_t mwd = __ballot_sync(0xFFFFFFFFu, keep);
        if (lane == 0) g_mask[(size_t)layer * NWORD + wp * 4 + q] = mwd;
    }

    // ---- gather (4 edges in flight; tail clamps index, zeroes value) ----
    int cnt = g_cnt[w];
    if (cnt > EMAX) cnt = EMAX;
    const int2* ep = g_ell + (size_t)w * EMAX;
    float4 acc = make_float4(0.f, 0.f, 0.f, 0.f);
    for (int j = 0; j < cnt; j += 4) {
        int i1 = min(j + 1, cnt - 1);
        int i2 = min(j + 2, cnt - 1);
        int i3 = min(j + 3, cnt - 1);
        int2 c0 = ep[j], c1 = ep[i1], c2 = ep[i2], c3 = ep[i3];
        uint2 u0 = ((const uint2*)(g_ego_h + (size_t)c0.x * DIM))[dl];
        uint2 u1 = ((const uint2*)(g_ego_h + (size_t)c1.x * DIM))[dl];
        uint2 u2 = ((const uint2*)(g_ego_h + (size_t)c2.x * DIM))[dl];
        uint2 u3 = ((const uint2*)(g_ego_h + (size_t)c3.x * DIM))[dl];
        float4 x0 = h4_to_f4(u0);
        float4 x1 = h4_to_f4(u1);
        float4 x2 = h4_to_f4(u2);
        float4 x3 = h4_to_f4(u3);
        float v0 = __int_as_float(c0.y);
        float v1 = (j + 1 < cnt) ? __int_as_float(c1.y) : 0.f;
        float v2 = (j + 2 < cnt) ? __int_as_float(c2.y) : 0.f;
        float v3 = (j + 3 < cnt) ? __int_as_float(c3.y) : 0.f;
        acc.x += v0 * x0.x + v1 * x1.x + v2 * x2.x + v3 * x3.x;
        acc.y += v0 * x0.y + v1 * x1.y + v2 * x2.y + v3 * x3.y;
        acc.z += v0 * x0.z + v1 * x1.z + v2 * x2.z + v3 * x3.z;
        acc.w += v0 * x0.w + v1 * x1.w + v2 * x2.w + v3 * x3.w;
    }
    __half2 h0 = __floats2half2_rn(acc.x, acc.y);
    __half2 h1 = __floats2half2_rn(acc.z, acc.w);
    uint2 out;
    out.x = *(uint32_t*)&h0;
    out.y = *(uint32_t*)&h1;
    ((uint2*)(g_side_h + (size_t)w * DIM))[dl] = out;
}

// fp16 tensor-core combine (m16n8k16, fp32 accum) + fused dropout/norm epilogue.
// A[128x128] = [side | side*ego] fp16; B stored transposed [n][k] fp16.
// smem ~52.5 KB -> 4 CTAs/SM (occ 50%).
__global__ void __launch_bounds__(256)
combine_kernel(const float* __restrict__ Wg, const float* __restrict__ bg,
               const float* __restrict__ Wb, const float* __restrict__ bb,
               int layer, int write_ego) {
    extern __shared__ __half smem_h[];
    __half* sA  = smem_h;                 // 128 x AH halves
    __half* sBt = sA + RPB * AH;          // 64 x BH halves (Bt[n][k])
    float*  sbias = (float*)(sBt + 64 * BH);

    int tid  = threadIdx.x;
    int row0 = blockIdx.x * RPB;

    // ---- build Bt (fp16, transposed) + bias; gmem reads coalesced over n ----
    for (int i = tid; i < 8192; i += 256) {
        int k = i >> 6, n = i & 63;
        float v = (k < 64) ? Wg[k * 64 + n] : Wb[(k - 64) * 64 + n];
        sBt[n * BH + k] = __float2half(v);
    }
    if (tid < 64) sbias[tid] = bg[tid] + bb[tid];

    // ---- build A (fp16): cols 0..63 = side (copy), 64..127 = side*ego ----
    for (int i = tid; i < RPB * 16; i += 256) {
        int r = i >> 4, q = i & 15;
        int gr = row0 + r;
        uint2 s2 = make_uint2(0u, 0u), e2 = make_uint2(0u, 0u);
        if (gr < NTOT) {
            s2 = ((const uint2*)(g_side_h + (size_t)gr * DIM))[q];
            e2 = ((const uint2*)(g_ego_h  + (size_t)gr * DIM))[q];
        }
        *(uint2*)&sA[r * AH + q * 4] = s2;      // side plane: direct copy
        float4 s = h4_to_f4(s2), e = h4_to_f4(e2);
        __half2 p0 = __floats2half2_rn(s.x * e.x, s.y * e.y);
        __half2 p1 = __floats2half2_rn(s.z * e.z, s.w * e.w);
        uint2 pp;
        pp.x = *(uint32_t*)&p0;
        pp.y = *(uint32_t*)&p1;
        *(uint2*)&sA[r * AH + 64 + q * 4] = pp;
    }
    __syncthreads();

    int w    = tid >> 5;
    int lane = tid & 31;
    int g    = lane >> 2;       // group id 0..7
    int tg   = lane & 3;        // thread-in-group 0..3
    int wr   = w * 16;

    float c[8][4];
#pragma unroll
    for (int nt = 0; nt < 8; nt++) {
        int col0 = nt * 8 + tg * 2;
        float b0 = sbias[col0], b1 = sbias[col0 + 1];
        c[nt][0] = b0; c[nt][1] = b1;   // row g
        c[nt][2] = b0; c[nt][3] = b1;   // row g+8
    }

    const uint32_t* Aw = (const uint32_t*)sA;    // word view, row stride 68
    const uint32_t* Bw = (const uint32_t*)sBt;   // word view, row stride 68
#pragma unroll
    for (int ks = 0; ks < 8; ks++) {
        int kw = ks * 8;                          // word offset within row (16 halves)
        uint32_t a0 = Aw[(wr + g) * 68 + kw + tg];
        uint32_t a1 = Aw[(wr + g + 8) * 68 + kw + tg];
        uint32_t a2 = Aw[(wr + g) * 68 + kw + tg + 4];
        uint32_t a3 = Aw[(wr + g + 8) * 68 + kw + tg + 4];
#pragma unroll
        for (int nt = 0; nt < 8; nt++) {
            int nrow = nt * 8 + g;
            uint32_t b0 = Bw[nrow * 68 + kw + tg];
            uint32_t b1 = Bw[nrow * 68 + kw + tg + 4];
            mma_f16(c[nt], a0, a1, a2, a3, b0, b1);
        }
    }

    // ---- fused epilogue: leaky_relu -> dropout (bitmask) -> L2 norm ----
    int r0 = row0 + wr + g;
    int r1 = r0 + 8;
    const uint32_t* mb = g_mask + (size_t)layer * NWORD;
    uint2 m0 = (r0 < NTOT) ? *(const uint2*)&mb[2 * r0] : make_uint2(0u, 0u);
    uint2 m1 = (r1 < NTOT) ? *(const uint2*)&mb[2 * r1] : make_uint2(0u, 0u);

    float ss0 = 0.f, ss1 = 0.f;
#pragma unroll
    for (int nt = 0; nt < 8; nt++) {
        int col0 = nt * 8 + tg * 2;
#pragma unroll
        for (int q = 0; q < 2; q++) {
            int col = col0 + q;
            uint32_t bit0 = ((col < 32 ? m0.x : m0.y) >> (col & 31)) & 1u;
            uint32_t bit1 = ((col < 32 ? m1.x : m1.y) >> (col & 31)) & 1u;
            float a = c[nt][q];
            a = (a >= 0.f) ? a : 0.2f * a;
            a = bit0 ? a * (1.0f / 0.9f) : 0.f;
            c[nt][q] = a;
            ss0 += a * a;
            float b = c[nt][2 + q];
            b = (b >= 0.f) ? b : 0.2f * b;
            b = bit1 ? b * (1.0f / 0.9f) : 0.f;
            c[nt][2 + q] = b;
            ss1 += b * b;
        }
    }
    ss0 += __shfl_xor_sync(0xFFFFFFFFu, ss0, 1);
    ss0 += __shfl_xor_sync(0xFFFFFFFFu, ss0, 2);
    ss1 += __shfl_xor_sync(0xFFFFFFFFu, ss1, 1);
    ss1 += __shfl_xor_sync(0xFFFFFFFFu, ss1, 2);
    float inv0 = 1.0f / fmaxf(sqrtf(ss0), 1e-12f);
    float inv1 = 1.0f / fmaxf(sqrtf(ss1), 1e-12f);

    float* all0 = g_all + (size_t)r0 * CDIM2 + (size_t)layer * DIM;
    float* all1 = g_all + (size_t)r1 * CDIM2 + (size_t)layer * DIM;
#pragma unroll
    for (int nt = 0; nt < 8; nt++) {
        int col0 = nt * 8 + tg * 2;
        if (r0 < NTOT) {
            *(float2*)(all0 + col0) = make_float2(c[nt][0] * inv0, c[nt][1] * inv0);
            if (write_ego)
                *(__half2*)(g_ego_h + (size_t)r0 * DIM + col0) =
                    __floats2half2_rn(c[nt][0], c[nt][1]);
        }
        if (r1 < NTOT) {
            *(float2*)(all1 + col0) = make_float2(c[nt][2] * inv1, c[nt][3] * inv1);
            if (write_ego)
                *(__half2*)(g_ego_h + (size_t)r1 * DIM + col0) =
                    __floats2half2_rn(c[nt][2], c[nt][3]);
        }
    }
}

// warp per sample: BPR + reg partial sums. Concat = [raw emb | g_all(192)].
__global__ void loss_kernel(const float* __restrict__ ue0, const float* __restrict__ ie0,
                            const int* __restrict__ uid, const int* __restrict__ pid,
                            const int* __restrict__ nid) {
    int w    = (blockIdx.x * blockDim.x + threadIdx.x) >> 5;
    int lane = threadIdx.x & 31;
    if (w >= BSZ) return;
    int u = uid[w], p = pid[w], n = nid[w];
    const float* au = (lane < 8) ? ue0 + (size_t)u * DIM + lane * 8
                                 : g_all + (size_t)u * CDIM2 + lane * 8 - 64;
    const float* bp = (lane < 8) ? ie0 + (size_t)p * DIM + lane * 8
                                 : g_all + (size_t)(UNUM + p) * CDIM2 + lane * 8 - 64;
    const float* bn = (lane < 8) ? ie0 + (size_t)n * DIM + lane * 8
                                 : g_all + (size_t)(UNUM + n) * CDIM2 + lane * 8 - 64;
    float pos = 0.f, neg = 0.f;
#pragma unroll
    for (int t = 0; t < 2; t++) {
        float4 a = ((const float4*)au)[t];
        float4 b = ((const float4*)bp)[t];
        float4 c = ((const float4*)bn)[t];
        pos += a.x * b.x + a.y * b.y + a.z * b.z + a.w * b.w;
        neg += a.x * c.x + a.y * c.y + a.z * c.z + a.w * c.w;
    }
    float2 a0 = ((const float2*)(ue0 + (size_t)u * DIM))[lane];
    float2 b0 = ((const float2*)(ie0 + (size_t)p * DIM))[lane];
    float2 c0 = ((const float2*)(ie0 + (size_t)n * DIM))[lane];
    float rg = a0.x * a0.x + a0.y * a0.y + b0.x * b0.x + b0.y * b0.y + c0.x * c0.x + c0.y * c0.y;
#pragma unroll
    for (int o = 16; o; o >>= 1) {
        pos += __shfl_xor_sync(0xFFFFFFFFu, pos, o);
        neg += __shfl_xor_sync(0xFFFFFFFFu, neg, o);
        rg  += __shfl_xor_sync(0xFFFFFFFFu, rg,  o);
    }
    if (lane == 0) {
        float x = pos - neg;
        float ls = fminf(x, 0.f) - log1pf(expf(-fabsf(x)));  // stable log_sigmoid
        atomicAdd(&g_acc[0], ls);
        atomicAdd(&g_acc[1], rg);
    }
}

__global__ void fin_kernel(float* out, int osz) {
    float bpr = -g_acc[0] / (float)BSZ;
    float reg = 1e-4f * 0.5f * g_acc[1] / (float)BSZ;
    if (osz >= 3) { out[0] = bpr + reg; out[1] = bpr; out[2] = reg; }
    else          { out[0] = bpr + reg; }
}

// ---------------- launch ----------------
extern "C" void kernel_launch(void* const* d_in, const int* in_sizes, int n_in,
                              void* d_out, int out_size) {
    const float* user_emb = (const float*)d_in[0];
    const float* item_emb = (const float*)d_in[1];
    const float* W_gc     = (const float*)d_in[2];
    const float* b_gc     = (const float*)d_in[3];
    const float* W_bi     = (const float*)d_in[4];
    const float* b_bi     = (const float*)d_in[5];
    const float* val      = (const float*)d_in[6];
    const int*   row      = (const int*)d_in[7];
    const int*   col      = (const int*)d_in[8];
    const int*   uid      = (const int*)d_in[9];
    const int*   pid      = (const int*)d_in[10];
    const int*   nid      = (const int*)d_in[11];

    // derived threefry keys: base key = (0, 42); fold_in(d) = threefry(key, (0, d))
    uint32_t ke0, ke1;
    threefry2x32(0u, 42u, 0u, 0u, ke0, ke1);
    uint32_t mk0[NLAY], mk1[NLAY];
    for (int k = 0; k < NLAY; k++)
        threefry2x32(0u, 42u, 0u, (uint32_t)(k + 1), mk0[k], mk1[k]);

    const size_t SMEM = (RPB * AH + 64 * BH) * sizeof(__half) + 64 * sizeof(float); // ~52.5 KB
    static bool attr_set = false;
    if (!attr_set) {
        cudaFuncSetAttribute(combine_kernel, cudaFuncAttributeMaxDynamicSharedMemorySize, (int)SMEM);
        attr_set = true;
    }

    void* cnt_ptr = nullptr;
    cudaGetSymbolAddress(&cnt_ptr, g_cnt);

    cudaMemsetAsync(cnt_ptr, 0, NTOT * sizeof(int));
    init_kernel<<<(NELEM + 255) / 256, 256>>>(user_emb, item_emb);
    scatter_kernel<<<(NNZE + 255) / 256, 256>>>(val, row, col, ke0, ke1);

    for (int k = 0; k < NLAY; k++) {
        spmm_kernel<<<((NTOT / 2) * 32 + 255) / 256, 256>>>(mk0[k], mk1[k], k);
        combine_kernel<<<(NTOT + RPB - 1) / RPB, 256, SMEM>>>(
            W_gc + k * 4096, b_gc + k * 64, W_bi + k * 4096, b_bi + k * 64,
            k, (k != NLAY - 1) ? 1 : 0);
    }

    loss_kernel<<<(BSZ * 32 + 255) / 256, 256>>>(user_emb, item_emb, uid, pid, nid);
    fin_kernel<<<1, 1>>>((float*)d_out, out_size);
}